// round 9
// baseline (speedup 1.0000x reference)
#include <cuda_runtime.h>
#include <cstdint>

#define NUM_HEADS 8
#define IN_BITS   64
#define N_STATE   256
#define N_OUT     64
#define K_CONN    8
#define HASH      65536
#define BATCH     128
#define T_STEPS   128
#define TOTAL_IN  320   // IN_BITS + N_STATE

// Bit-packed threshold table: bit = (state_mem[n][a] >= 0.5). 2 MB, L2-resident.
__device__ uint32_t g_state_bits[N_STATE * (HASH / 32)];

// ---------------------------------------------------------------------------
// Prologue: pack state_mem (64 MB floats) into g_state_bits (2 MB). HBM-bound.
// ---------------------------------------------------------------------------
__global__ void pack_state_mem_kernel(const float* __restrict__ sm)
{
    const int tid  = blockIdx.x * blockDim.x + threadIdx.x;
    const int lane = threadIdx.x & 31;
    const int gw   = tid >> 5;
    const size_t base = (size_t)gw * 128;
    #pragma unroll
    for (int j = 0; j < 4; j++) {
        float v = sm[base + (size_t)j * 32 + lane];
        uint32_t b = __ballot_sync(0xFFFFFFFFu, v >= 0.5f);
        if (lane == 0) g_state_bits[gw * 4 + j] = b;
    }
}

// ---------------------------------------------------------------------------
// Main scan. One CTA per batch, 256 threads, thread t = neuron t.
// Pipelined split-state dot:
//   exposed per step: dotS1 (64 dp2a) -> addr -> LDG -> bar1
//   hidden in the gather/barrier window: WIN_ACC(k+1) and dotS0(k+1)
// State halves: S0 = neurons 0..127 (produced by g0 = threads < 128),
//               S1 = neurons 128..255 (g1). Double-buffered; 2 barriers/step.
// ---------------------------------------------------------------------------
__global__ __launch_bounds__(256, 1)
void ram_scan_kernel(const int*   __restrict__ bits,          // (B, T*64)
                     const int*   __restrict__ state_coeffs,  // (256, 320)
                     const int*   __restrict__ head_conn,     // (8, 64, 8)
                     const int*   __restrict__ head_coeffs,   // (8, 64, 8)
                     const float* __restrict__ head_mem,      // (8, 64, 65536)
                     float*       __restrict__ out)           // (B, 64)
{
    __shared__ uint32_t win_words[T_STEPS * 16]; // 8 KB: all window bits as bytes
    __shared__ uint32_t stbuf[2][64];            // double-buffered 256 state bytes

    const int b = blockIdx.x;
    const int t = threadIdx.x;                   // neuron id

    // ---- expand all T windows to 0/1 bytes ----
    const int4* bits4 = reinterpret_cast<const int4*>(bits + (size_t)b * (T_STEPS * IN_BITS));
    for (int w = t; w < T_STEPS * 16; w += 256) {
        int4 v = bits4[w];
        win_words[w] = (uint32_t)(v.x & 1) | ((uint32_t)(v.y & 1) << 8)
                     | ((uint32_t)(v.z & 1) << 16) | ((uint32_t)(v.w & 1) << 24);
    }
    if (t < 128) { stbuf[0][t >> 1] = 0u; stbuf[1][t >> 1] = 0u; }

    // ---- coefficients as u16 pairs for dp2a (exact u32 accumulation) ----
    uint32_t w2[32], cA[64], cB[64];   // window / state S0 / state S1
    {
        const int4* crow = reinterpret_cast<const int4*>(state_coeffs + (size_t)t * TOTAL_IN);
        #pragma unroll
        for (int k = 0; k < 16; k++) {
            int4 v = crow[k];
            w2[2*k]   = (uint32_t)(v.x & 0xFFFF) | ((uint32_t)v.y << 16);
            w2[2*k+1] = (uint32_t)(v.z & 0xFFFF) | ((uint32_t)v.w << 16);
        }
        #pragma unroll
        for (int k = 0; k < 32; k++) {           // S0: inputs 64..191
            int4 v = crow[16 + k];
            cA[2*k]   = (uint32_t)(v.x & 0xFFFF) | ((uint32_t)v.y << 16);
            cA[2*k+1] = (uint32_t)(v.z & 0xFFFF) | ((uint32_t)v.w << 16);
        }
        #pragma unroll
        for (int k = 0; k < 32; k++) {           // S1: inputs 192..319
            int4 v = crow[48 + k];
            cB[2*k]   = (uint32_t)(v.x & 0xFFFF) | ((uint32_t)v.y << 16);
            cB[2*k+1] = (uint32_t)(v.z & 0xFFFF) | ((uint32_t)v.w << 16);
        }
    }
    __syncthreads();   // win_words + stbuf ready

    const uint4* wv = reinterpret_cast<const uint4*>(win_words); // 4 uint4 / step

    #define WIN_ACC(STEP, OUTV)                                                 \
    {                                                                           \
        uint32_t _a0 = 0u, _a1 = 0u, _a2 = 0u, _a3 = 0u;                        \
        _Pragma("unroll")                                                       \
        for (int q = 0; q < 4; q++) {                                           \
            uint4 x = wv[(STEP) * 4 + q];                                       \
            _a0 = __dp2a_lo(w2[8*q+0], x.x, _a0); _a0 = __dp2a_hi(w2[8*q+1], x.x, _a0); \
            _a1 = __dp2a_lo(w2[8*q+2], x.y, _a1); _a1 = __dp2a_hi(w2[8*q+3], x.y, _a1); \
            _a2 = __dp2a_lo(w2[8*q+4], x.z, _a2); _a2 = __dp2a_hi(w2[8*q+5], x.z, _a2); \
            _a3 = __dp2a_lo(w2[8*q+6], x.w, _a3); _a3 = __dp2a_hi(w2[8*q+7], x.w, _a3); \
        }                                                                       \
        (OUTV) = (_a0 + _a1) + (_a2 + _a3);                                     \
    }

    // half-state dot: 64 dp2a over 8 uint4 starting at word offset OFF
    #define HALF_DOT(BUF, OFF, C, OUTV)                                         \
    {                                                                           \
        const uint4* _s4 = reinterpret_cast<const uint4*>(BUF) + (OFF);         \
        uint32_t _a0 = 0u, _a1 = 0u, _a2 = 0u, _a3 = 0u;                        \
        _Pragma("unroll")                                                       \
        for (int q = 0; q < 8; q++) {                                           \
            uint4 x = _s4[q];                                                   \
            _a0 = __dp2a_lo((C)[8*q+0], x.x, _a0); _a0 = __dp2a_hi((C)[8*q+1], x.x, _a0); \
            _a1 = __dp2a_lo((C)[8*q+2], x.y, _a1); _a1 = __dp2a_hi((C)[8*q+3], x.y, _a1); \
            _a2 = __dp2a_lo((C)[8*q+4], x.z, _a2); _a2 = __dp2a_hi((C)[8*q+5], x.z, _a2); \
            _a3 = __dp2a_lo((C)[8*q+6], x.w, _a3); _a3 = __dp2a_hi((C)[8*q+7], x.w, _a3); \
        }                                                                       \
        (OUTV) = (_a0 + _a1) + (_a2 + _a3);                                     \
    }

    const uint32_t* prow = g_state_bits + ((size_t)t << 11);   // 2048 words/row

    // acc0(k) = dotS0(k) + window(k); state(0) = 0 -> just window(0)
    uint32_t acc0;
    WIN_ACC(0, acc0);

    #pragma unroll 2
    for (int step = 0; step < T_STEPS; step++) {
        const int cur = step & 1, nxt = cur ^ 1;

        // exposed: dot over S1(k), then address
        uint32_t d1;
        HALF_DOT(stbuf[cur], 8, cB, d1);
        const uint32_t s    = acc0 + d1;
        const uint32_t addr = s & 0xFFFFu;

        // random gather (L2-resident 2 MB table)
        const uint32_t wword = __ldg(prow + (addr >> 5));

        // gather shadow 1: next step's window dot
        uint32_t wacc;
        WIN_ACC((step + 1) & (T_STEPS - 1), wacc);

        uint8_t* stn = reinterpret_cast<uint8_t*>(stbuf[nxt]);
        if (t < 128)   // g0: own word needed now
            stn[t] = (uint8_t)((wword >> (addr & 31u)) & 1u);
        __syncthreads();   // bar1: S0(k+1) visible; g1 arrived after LDG issue

        if (t >= 128)  // g1: word arrived during bar1 wait; S1 region disjoint from S0 reads
            stn[t] = (uint8_t)((wword >> (addr & 31u)) & 1u);

        // gather shadow 2: dot over S0(k+1) while g1 stores drain
        uint32_t d0;
        HALF_DOT(stbuf[nxt], 0, cA, d0);
        acc0 = d0 + wacc;

        __syncthreads();   // bar2: S1(k+1) visible; old buffer free
    }

    // ---- Head readout (threads 0..63); T even -> final state in stbuf[0] ----
    if (t < N_OUT) {
        const uint8_t* state_b = reinterpret_cast<const uint8_t*>(stbuf[0]);
        const int* lw = bits + (size_t)b * (T_STEPS * IN_BITS) + (T_STEPS * IN_BITS - 3);
        const int hidx = (lw[0] << 2) + (lw[1] << 1) + lw[2];    // 0..7
        const int o    = t;
        const int base = (hidx * N_OUT + o) * K_CONN;
        uint32_t addr = 0u;
        #pragma unroll
        for (int k = 0; k < K_CONN; k++) {
            int conn = __ldg(head_conn + base + k);
            uint32_t c = (uint32_t)__ldg(head_coeffs + base + k);
            addr += state_b[conn] ? c : 0u;
        }
        addr &= 0xFFFFu;
        out[(size_t)b * N_OUT + o] =
            __ldg(head_mem + (((size_t)(hidx * N_OUT + o)) << 16) + addr);
    }
    #undef WIN_ACC
    #undef HALF_DOT
}

extern "C" void kernel_launch(void* const* d_in, const int* in_sizes, int n_in,
                              void* d_out, int out_size)
{
    const int*   bits         = (const int*)  d_in[0];
    const int*   state_coeffs = (const int*)  d_in[1];
    const float* state_mem    = (const float*)d_in[2];
    const int*   head_conn    = (const int*)  d_in[3];
    const int*   head_coeffs  = (const int*)  d_in[4];
    const float* head_mem     = (const float*)d_in[5];
    float*       out          = (float*)      d_out;

    pack_state_mem_kernel<<<16384, 256>>>(state_mem);
    ram_scan_kernel<<<BATCH, 256>>>(bits, state_coeffs,
                                    head_conn, head_coeffs, head_mem, out);
}